// round 13
// baseline (speedup 1.0000x reference)
#include <cuda_runtime.h>
#include <cuda_bf16.h>
#include <cuda_fp16.h>
#include <cstdint>

// ---------------------------------------------------------------------------
// HiddenRRGCN round 13: R12 + 8-edge gather chunks (2x MLP in the latency-
// exposed aggregation phase) + zero_i folded into convert_h_all.
// ---------------------------------------------------------------------------

static constexpr int NCn = 100000;
static constexpr int NGn = 8000;
static constexpr int E_CG = 1500000;
static constexpr int E_GC = 1500000;
static constexpr int E_CC = 1000000;
static constexpr int E_GG = 200000;
static constexpr int NDEG = 2 * NCn + 2 * NGn;
static constexpr int E_ALL = E_CG + E_GC + E_CC + E_GG;

static constexpr int OFF_GC = 0;
static constexpr int OFF_CC = NCn;
static constexpr int OFF_CG = 2 * NCn;
static constexpr int OFF_GG = 2 * NCn + NGn;

static constexpr int Q1 = E_GC / 4;
static constexpr int Q2 = Q1 + E_CC / 4;
static constexpr int Q3 = Q2 + E_CG / 4;
static constexpr int QALL = E_ALL / 4;

// ---- static scratch -------------------------------------------------------
__device__ int   g_deg[NDEG];
__device__ float g_inv[NDEG];
__device__ int   g_cur[NDEG];
__device__ int   g_rp[NDEG + 1];
__device__ int   g_col[E_ALL];
__device__ int   g_bsum[256];
__device__ int   g_bscan[257];
__device__ __align__(16) __half g_h16c[(size_t)NCn * 128];
__device__ __align__(16) __half g_h16g[(size_t)NGn * 128];
__device__ __align__(16) __half g_m16c[(size_t)NCn * 128];
__device__ __align__(16) __half g_m16g[(size_t)NGn * 128];
__device__ __align__(16) __nv_bfloat16 g_Whi[4][128 * 128];  // gc, cc, cg, gg
__device__ __align__(16) __nv_bfloat16 g_Wlo[4][128 * 128];

// ---------------------------------------------------------------------------
// convert fp32 features -> fp16 tables; ALSO zeroes g_deg (no dependency)
__global__ void convert_h_all(const float4* __restrict__ hc, const float4* __restrict__ hg) {
    int i = blockIdx.x * blockDim.x + threadIdx.x;
    const int NC4 = NCn * 32;
    const int NG4 = NGn * 32;
    if (i < NDEG) g_deg[i] = 0;
    if (i < NC4) {
        float4 v = __ldg(hc + i);
        __half2 a = __floats2half2_rn(v.x, v.y);
        __half2 b = __floats2half2_rn(v.z, v.w);
        reinterpret_cast<uint2*>(g_h16c)[i] = make_uint2(
            *reinterpret_cast<uint32_t*>(&a), *reinterpret_cast<uint32_t*>(&b));
    } else if (i < NC4 + NG4) {
        int j = i - NC4;
        float4 v = __ldg(hg + j);
        __half2 a = __floats2half2_rn(v.x, v.y);
        __half2 b = __floats2half2_rn(v.z, v.w);
        reinterpret_cast<uint2*>(g_h16g)[j] = make_uint2(
            *reinterpret_cast<uint32_t*>(&a), *reinterpret_cast<uint32_t*>(&b));
    }
}

__global__ void count_deg_all(const int4* __restrict__ dst_gc, const int4* __restrict__ dst_cc,
                              const int4* __restrict__ dst_cg, const int4* __restrict__ dst_gg) {
    int i = blockIdx.x * blockDim.x + threadIdx.x;
    if (i >= QALL) return;
    int4 d; int off;
    if (i < Q1)      { d = __ldg(dst_gc + i);      off = OFF_GC; }
    else if (i < Q2) { d = __ldg(dst_cc + i - Q1); off = OFF_CC; }
    else if (i < Q3) { d = __ldg(dst_cg + i - Q2); off = OFF_CG; }
    else             { d = __ldg(dst_gg + i - Q3); off = OFF_GG; }
    atomicAdd(&g_deg[off + d.x], 1);
    atomicAdd(&g_deg[off + d.y], 1);
    atomicAdd(&g_deg[off + d.z], 1);
    atomicAdd(&g_deg[off + d.w], 1);
}

__global__ void convert_w_all(const float* __restrict__ W0, const float* __restrict__ W1,
                              const float* __restrict__ W2, const float* __restrict__ W3) {
    int i = blockIdx.x * blockDim.x + threadIdx.x;
    if (i >= 4 * 16384) return;
    int m = i >> 14;
    int j = i & 16383;
    const float* W = (m == 0) ? W0 : (m == 1) ? W1 : (m == 2) ? W2 : W3;
    float v = W[j];
    __nv_bfloat16 h = __float2bfloat16_rn(v);
    g_Whi[m][j] = h;
    g_Wlo[m][j] = __float2bfloat16_rn(v - __bfloat162float(h));
}

__global__ void scan_part1(const int* __restrict__ in, int* __restrict__ bsum, int n) {
    __shared__ int ws[32];
    int tid = threadIdx.x;
    int i = blockIdx.x * 1024 + tid;
    int v = (i < n) ? in[i] : 0;
    if (i < n) g_inv[i] = 1.0f / (float)(v > 0 ? v : 1);
    int x = v;
#pragma unroll
    for (int o = 16; o > 0; o >>= 1) x += __shfl_xor_sync(0xffffffffu, x, o);
    if ((tid & 31) == 0) ws[tid >> 5] = x;
    __syncthreads();
    if (tid < 32) {
        int s = ws[tid];
#pragma unroll
        for (int o = 16; o > 0; o >>= 1) s += __shfl_xor_sync(0xffffffffu, s, o);
        if (tid == 0) bsum[blockIdx.x] = s;
    }
}

__global__ void exscan_small(const int* __restrict__ in, int* __restrict__ out, int n) {
    __shared__ int ws[32];
    int tid = threadIdx.x;
    int v = (tid < n) ? in[tid] : 0;
    int x = v;
#pragma unroll
    for (int o = 1; o < 32; o <<= 1) {
        int t = __shfl_up_sync(0xffffffffu, x, o);
        if ((tid & 31) >= o) x += t;
    }
    if ((tid & 31) == 31) ws[tid >> 5] = x;
    __syncthreads();
    if (tid < 32) {
        int s = ws[tid];
#pragma unroll
        for (int o = 1; o < 32; o <<= 1) {
            int t = __shfl_up_sync(0xffffffffu, s, o);
            if (tid >= o) s += t;
        }
        ws[tid] = s;
    }
    __syncthreads();
    int woff = (tid >= 32) ? ws[(tid >> 5) - 1] : 0;
    if (tid < n) out[tid] = x - v + woff;
    if (tid == n - 1) out[n] = x + woff;
}

__global__ void scan_part3(const int* __restrict__ in, const int* __restrict__ boff,
                           int* __restrict__ out, int n) {
    __shared__ int ws[32];
    int tid = threadIdx.x;
    int i = blockIdx.x * 1024 + tid;
    int v = (i < n) ? in[i] : 0;
    int x = v;
#pragma unroll
    for (int o = 1; o < 32; o <<= 1) {
        int t = __shfl_up_sync(0xffffffffu, x, o);
        if ((tid & 31) >= o) x += t;
    }
    if ((tid & 31) == 31) ws[tid >> 5] = x;
    __syncthreads();
    if (tid < 32) {
        int s = ws[tid];
#pragma unroll
        for (int o = 1; o < 32; o <<= 1) {
            int t = __shfl_up_sync(0xffffffffu, s, o);
            if (tid >= o) s += t;
        }
        ws[tid] = s;
    }
    __syncthreads();
    int woff = ((tid >> 5) > 0) ? ws[(tid >> 5) - 1] : 0;
    int excl = x - v + woff + boff[blockIdx.x];
    if (i < n) {
        out[i] = excl;
        g_cur[i] = excl;
    }
    if (i == n - 1) out[n] = excl + v;
}

__global__ void fill_csr_all(const int4* __restrict__ src_gc, const int4* __restrict__ dst_gc,
                             const int4* __restrict__ src_cc, const int4* __restrict__ dst_cc,
                             const int4* __restrict__ src_cg, const int4* __restrict__ dst_cg,
                             const int4* __restrict__ src_gg, const int4* __restrict__ dst_gg) {
    int i = blockIdx.x * blockDim.x + threadIdx.x;
    if (i >= QALL) return;
    int4 s, d; int off;
    if (i < Q1)      { s = __ldg(src_gc + i);      d = __ldg(dst_gc + i);      off = OFF_GC; }
    else if (i < Q2) { s = __ldg(src_cc + i - Q1); d = __ldg(dst_cc + i - Q1); off = OFF_CC; }
    else if (i < Q3) { s = __ldg(src_cg + i - Q2); d = __ldg(dst_cg + i - Q2); off = OFF_CG; }
    else             { s = __ldg(src_gg + i - Q3); d = __ldg(dst_gg + i - Q3); off = OFF_GG; }
    int p0 = atomicAdd(&g_cur[off + d.x], 1);
    int p1 = atomicAdd(&g_cur[off + d.y], 1);
    int p2 = atomicAdd(&g_cur[off + d.z], 1);
    int p3 = atomicAdd(&g_cur[off + d.w], 1);
    g_col[p0] = s.x;
    g_col[p1] = s.y;
    g_col[p2] = s.z;
    g_col[p3] = s.w;
}

// ---------------------------------------------------------------------------
__device__ __forceinline__ uint32_t s2u(const void* p) {
    return (uint32_t)__cvta_generic_to_shared(p);
}

__device__ __forceinline__ void ldsm_x4(uint32_t addr, uint32_t& r0, uint32_t& r1,
                                        uint32_t& r2, uint32_t& r3) {
    asm volatile("ldmatrix.sync.aligned.m8n8.x4.shared.b16 {%0,%1,%2,%3}, [%4];"
                 : "=r"(r0), "=r"(r1), "=r"(r2), "=r"(r3) : "r"(addr));
}

__device__ __forceinline__ void ldsm_x2t(uint32_t addr, uint32_t& r0, uint32_t& r1) {
    asm volatile("ldmatrix.sync.aligned.m8n8.x2.trans.shared.b16 {%0,%1}, [%2];"
                 : "=r"(r0), "=r"(r1) : "r"(addr));
}

__device__ __forceinline__ void mma_bf16(float* c, const uint32_t* a, const uint32_t* b) {
    asm volatile(
        "mma.sync.aligned.m16n8k16.row.col.f32.bf16.bf16.f32 "
        "{%0,%1,%2,%3}, {%4,%5,%6,%7}, {%8,%9}, {%0,%1,%2,%3};"
        : "+f"(c[0]), "+f"(c[1]), "+f"(c[2]), "+f"(c[3])
        : "r"(a[0]), "r"(a[1]), "r"(a[2]), "r"(a[3]), "r"(b[0]), "r"(b[1]));
}

__device__ __forceinline__ void acc_h4(float4& a, uint2 v) {
    float2 p = __half22float2(*reinterpret_cast<__half2*>(&v.x));
    float2 q = __half22float2(*reinterpret_cast<__half2*>(&v.y));
    a.x += p.x; a.y += p.y; a.z += q.x; a.w += q.y;
}

struct Side {
    const int* rpA; const int* rpB;
    const __half* hA; const float* invA;
    const __half* hB; const float* invB;
    const __nv_bfloat16 *WAhi, *WAlo, *WBhi, *WBlo;
    const float *bias, *lns, *lnb;
    void* out;
    int n;
};

static constexpr int TM = 64;
static constexpr int XSTR = 136;
static constexpr int WSTR = 136;
static constexpr int FUSED_SMEM =
    (TM * XSTR * 2) * 2 +
    (64 * WSTR * 2) * 2 +
    (TM * 4 * 4) * 2 +
    TM * 2 * 4;

template <bool OUT_HALF>
__global__ void __launch_bounds__(256, 3)
fused_layer(const Side cs, const Side gs, const int* __restrict__ colAll, int nGeneBlocks) {
    constexpr int NT = 4;
    constexpr int WARPS_N = 4;

    extern __shared__ char smem[];
    __nv_bfloat16* Xhi = reinterpret_cast<__nv_bfloat16*>(smem);
    __nv_bfloat16* Xlo = Xhi + TM * XSTR;
    __nv_bfloat16* Whs = Xlo + TM * XSTR;
    __nv_bfloat16* Wls = Whs + 64 * WSTR;
    float* spsum = reinterpret_cast<float*>(Wls + 64 * WSTR);
    float* spsq  = spsum + TM * WARPS_N;
    float* stats = spsq + TM * WARPS_N;

    const bool isGene = (int)blockIdx.x < nGeneBlocks;
    const Side* S = isGene ? &gs : &cs;
    const int blk = isGene ? blockIdx.x : (blockIdx.x - nGeneBlocks);
    const int row0 = blk * TM;
    const int n = S->n;

    const int tid = threadIdx.x;
    const int lane = tid & 31;
    const int wid = tid >> 5;
    const int warp_m = (wid & 1) * 32;
    const int nwid = wid >> 1;
    const int warp_n = nwid * 32;

    uint32_t xhi_base[2], xlo_base[2];
#pragma unroll
    for (int mi = 0; mi < 2; ++mi) {
        int row = warp_m + mi * 16 + (lane & 15);
        int koff = (lane >> 4) << 3;
        xhi_base[mi] = s2u(Xhi) + (row * XSTR + koff) * 2;
        xlo_base[mi] = s2u(Xlo) + (row * XSTR + koff) * 2;
    }
    uint32_t wh_base[NT], wl_base[NT];
#pragma unroll
    for (int ni = 0; ni < NT; ++ni) {
        int off = ((lane & 15) * WSTR + warp_n + ni * 8) * 2;
        wh_base[ni] = s2u(Whs) + off;
        wl_base[ni] = s2u(Wls) + off;
    }

    float acc[2][NT][4];
#pragma unroll
    for (int mi = 0; mi < 2; ++mi)
#pragma unroll
        for (int ni = 0; ni < NT; ++ni)
#pragma unroll
            for (int j = 0; j < 4; ++j) acc[mi][ni][j] = 0.f;

#pragma unroll
    for (int half = 0; half < 2; ++half) {
        const int* rp = half ? S->rpB : S->rpA;
        const uint2* hp = reinterpret_cast<const uint2*>(half ? S->hB : S->hA);
        const float* invp = half ? S->invB : S->invA;
        const __nv_bfloat16* Whig = half ? S->WBhi : S->WAhi;
        const __nv_bfloat16* Wlog = half ? S->WBlo : S->WAlo;

        __syncthreads();   // previous half's X reads complete

        // ---- aggregation: predicated chunks of 8, cols software-pipelined ----
        for (int r = wid; r < TM; r += 8) {
            int row = row0 + r;
            float4 a0 = make_float4(0.f, 0.f, 0.f, 0.f);
            float4 a1 = a0, a2 = a0, a3 = a0;
            float sc = 0.f;
            if (row < n) {
                int e = __ldg(rp + row);
                const int eEnd = __ldg(rp + row + 1);
                sc = __ldg(invp + row);
                if (e < eEnd) {
                    const int last = eEnd - 1;
                    int s[8];
#pragma unroll
                    for (int j = 0; j < 8; ++j) s[j] = __ldg(colAll + min(e + j, last));
                    while (e < eEnd) {
                        const int en = e + 8;
                        const uint2 z = make_uint2(0u, 0u);
                        uint2 v[8];
                        v[0] = __ldg(hp + (size_t)s[0] * 32 + lane);
#pragma unroll
                        for (int j = 1; j < 8; ++j)
                            v[j] = (e + j < eEnd) ? __ldg(hp + (size_t)s[j] * 32 + lane) : z;
                        if (en < eEnd) {
#pragma unroll
                            for (int j = 0; j < 8; ++j)
                                s[j] = __ldg(colAll + min(en + j, last));
                        }
                        acc_h4(a0, v[0]);
                        acc_h4(a1, v[1]);
                        acc_h4(a2, v[2]);
                        acc_h4(a3, v[3]);
                        acc_h4(a0, v[4]);
                        acc_h4(a1, v[5]);
                        acc_h4(a2, v[6]);
                        acc_h4(a3, v[7]);
                        e = en;
                    }
                }
            }
            float vv[4] = {(a0.x + a1.x + a2.x + a3.x) * sc,
                           (a0.y + a1.y + a2.y + a3.y) * sc,
                           (a0.z + a1.z + a2.z + a3.z) * sc,
                           (a0.w + a1.w + a2.w + a3.w) * sc};
            __nv_bfloat16 hi4[4], lo4[4];
#pragma unroll
            for (int q = 0; q < 4; ++q) {
                __nv_bfloat16 h = __float2bfloat16_rn(vv[q]);
                hi4[q] = h;
                lo4[q] = __float2bfloat16_rn(vv[q] - __bfloat162float(h));
            }
            int xo = r * XSTR + lane * 4;
            *reinterpret_cast<uint2*>(Xhi + xo) = *reinterpret_cast<uint2*>(hi4);
            *reinterpret_cast<uint2*>(Xlo + xo) = *reinterpret_cast<uint2*>(lo4);
        }

        // ---- GEMM: 2 W tiles of 64 K-rows ----
#pragma unroll
        for (int kt2 = 0; kt2 < 2; ++kt2) {
            const __nv_bfloat16* Wghi = Whig + kt2 * 64 * 128;
            const __nv_bfloat16* Wglo = Wlog + kt2 * 64 * 128;
            __syncthreads();
#pragma unroll
            for (int c4 = 0; c4 < 4; ++c4) {
                int c = tid + c4 * 256;
                int wr = c >> 4;
                int wc = (c & 15) * 8;
                *reinterpret_cast<uint4*>(Whs + wr * WSTR + wc) =
                    __ldg(reinterpret_cast<const uint4*>(Wghi + wr * 128 + wc));
                *reinterpret_cast<uint4*>(Wls + wr * WSTR + wc) =
                    __ldg(reinterpret_cast<const uint4*>(Wglo + wr * 128 + wc));
            }
            __syncthreads();

#pragma unroll
            for (int ks = 0; ks < 4; ++ks) {
                int k0 = kt2 * 64 + ks * 16;
                uint32_t ah[2][4], al[2][4];
#pragma unroll
                for (int mi = 0; mi < 2; ++mi) {
                    ldsm_x4(xhi_base[mi] + k0 * 2, ah[mi][0], ah[mi][1], ah[mi][2], ah[mi][3]);
                    ldsm_x4(xlo_base[mi] + k0 * 2, al[mi][0], al[mi][1], al[mi][2], al[mi][3]);
                }
#pragma unroll
                for (int ni = 0; ni < NT; ++ni) {
                    uint32_t bh[2], bl[2];
                    ldsm_x2t(wh_base[ni] + (ks * 16) * WSTR * 2, bh[0], bh[1]);
                    ldsm_x2t(wl_base[ni] + (ks * 16) * WSTR * 2, bl[0], bl[1]);
#pragma unroll
                    for (int mi = 0; mi < 2; ++mi) {
                        mma_bf16(acc[mi][ni], ah[mi], bh);
                        mma_bf16(acc[mi][ni], ah[mi], bl);
                        mma_bf16(acc[mi][ni], al[mi], bh);
                    }
                }
            }
        }
    }

    // ---- epilogue ----
    const float* bias = S->bias;
    const float* lns = S->lns;
    const float* lnb = S->lnb;

    float2 bias2[NT], lns2[NT], lnb2[NT];
#pragma unroll
    for (int ni = 0; ni < NT; ++ni) {
        int col = warp_n + ni * 8 + (lane & 3) * 2;
        bias2[ni] = *reinterpret_cast<const float2*>(bias + col);
        lns2[ni] = *reinterpret_cast<const float2*>(lns + col);
        lnb2[ni] = *reinterpret_cast<const float2*>(lnb + col);
    }

#pragma unroll
    for (int mi = 0; mi < 2; ++mi)
#pragma unroll
        for (int rh = 0; rh < 2; ++rh) {
            float s = 0.f, q = 0.f;
#pragma unroll
            for (int ni = 0; ni < NT; ++ni) {
                float v0 = acc[mi][ni][rh * 2 + 0] + bias2[ni].x;
                float v1 = acc[mi][ni][rh * 2 + 1] + bias2[ni].y;
                v0 = (v0 >= 0.f) ? v0 : 0.05f * v0;
                v1 = (v1 >= 0.f) ? v1 : 0.05f * v1;
                acc[mi][ni][rh * 2 + 0] = v0;
                acc[mi][ni][rh * 2 + 1] = v1;
                s += v0 + v1;
                q += v0 * v0 + v1 * v1;
            }
#pragma unroll
            for (int o = 1; o < 4; o <<= 1) {
                s += __shfl_xor_sync(0xffffffffu, s, o);
                q += __shfl_xor_sync(0xffffffffu, q, o);
            }
            if ((lane & 3) == 0) {
                int rl = warp_m + mi * 16 + (lane >> 2) + rh * 8;
                spsum[rl * WARPS_N + nwid] = s;
                spsq[rl * WARPS_N + nwid] = q;
            }
        }
    __syncthreads();

    if (tid < TM) {
        float s = 0.f, q = 0.f;
#pragma unroll
        for (int i = 0; i < WARPS_N; ++i) {
            s += spsum[tid * WARPS_N + i];
            q += spsq[tid * WARPS_N + i];
        }
        float mean = s * (1.f / 128.f);
        float var = q * (1.f / 128.f) - mean * mean;
        stats[tid * 2] = mean;
        stats[tid * 2 + 1] = rsqrtf(var + 1e-5f);
    }
    __syncthreads();

#pragma unroll
    for (int mi = 0; mi < 2; ++mi)
#pragma unroll
        for (int rh = 0; rh < 2; ++rh) {
            int rl = warp_m + mi * 16 + (lane >> 2) + rh * 8;
            int row = row0 + rl;
            if (row < n) {
                float mean = stats[rl * 2];
                float rstd = stats[rl * 2 + 1];
#pragma unroll
                for (int ni = 0; ni < NT; ++ni) {
                    int col = warp_n + ni * 8 + (lane & 3) * 2;
                    float y0 = (acc[mi][ni][rh * 2 + 0] - mean) * rstd * lns2[ni].x + lnb2[ni].x;
                    float y1 = (acc[mi][ni][rh * 2 + 1] - mean) * rstd * lns2[ni].y + lnb2[ni].y;
                    if (OUT_HALF) {
                        __half2 y2 = __floats2half2_rn(y0, y1);
                        *reinterpret_cast<__half2*>(
                            reinterpret_cast<__half*>(S->out) + (size_t)row * 128 + col) = y2;
                    } else {
                        *reinterpret_cast<float2*>(
                            reinterpret_cast<float*>(S->out) + (size_t)row * 128 + col) =
                            make_float2(y0, y1);
                    }
                }
            }
        }
}

// ---------------------------------------------------------------------------
extern "C" void kernel_launch(void* const* d_in, const int* in_sizes, int n_in,
                              void* d_out, int out_size) {
    const float* h_cell = (const float*)d_in[0];
    const float* h_gene = (const float*)d_in[1];
    const int* src_cg = (const int*)d_in[2];
    const int* dst_cg = (const int*)d_in[3];
    const int* src_gc = (const int*)d_in[4];
    const int* dst_gc = (const int*)d_in[5];
    const int* src_cc = (const int*)d_in[6];
    const int* dst_cc = (const int*)d_in[7];
    const int* src_gg = (const int*)d_in[8];
    const int* dst_gg = (const int*)d_in[9];
    const float* W_cg = (const float*)d_in[10];
    const float* W_gc = (const float*)d_in[11];
    const float* W_cc = (const float*)d_in[12];
    const float* W_gg = (const float*)d_in[13];
    const float* b_cell = (const float*)d_in[14];
    const float* b_gene = (const float*)d_in[15];
    const float* ln_s_cell = (const float*)d_in[16];
    const float* ln_b_cell = (const float*)d_in[17];
    const float* ln_s_gene = (const float*)d_in[18];
    const float* ln_b_gene = (const float*)d_in[19];
    float* out = (float*)d_out;

    int *rp, *bsum, *bscan, *col, *deg;
    float *inv;
    __half *h16c, *h16g, *m16c, *m16g;
    __nv_bfloat16 *Whi, *Wlo;
    cudaGetSymbolAddress((void**)&deg, g_deg);
    cudaGetSymbolAddress((void**)&rp, g_rp);
    cudaGetSymbolAddress((void**)&col, g_col);
    cudaGetSymbolAddress((void**)&bsum, g_bsum);
    cudaGetSymbolAddress((void**)&bscan, g_bscan);
    cudaGetSymbolAddress((void**)&inv, g_inv);
    cudaGetSymbolAddress((void**)&h16c, g_h16c);
    cudaGetSymbolAddress((void**)&h16g, g_h16g);
    cudaGetSymbolAddress((void**)&m16c, g_m16c);
    cudaGetSymbolAddress((void**)&m16g, g_m16g);
    cudaGetSymbolAddress((void**)&Whi, g_Whi);
    cudaGetSymbolAddress((void**)&Wlo, g_Wlo);

    cudaFuncSetAttribute(fused_layer<true>, cudaFuncAttributeMaxDynamicSharedMemorySize, FUSED_SMEM);
    cudaFuncSetAttribute(fused_layer<false>, cudaFuncAttributeMaxDynamicSharedMemorySize, FUSED_SMEM);

    // ---- setup ----
    convert_w_all<<<(4 * 16384 + 255) / 256, 256>>>(W_gc, W_cc, W_cg, W_gg);
    convert_h_all<<<((NCn + NGn) * 32 + 255) / 256, 256>>>(
        (const float4*)h_cell, (const float4*)h_gene);   // also zeroes g_deg
    count_deg_all<<<(QALL + 255) / 256, 256>>>(
        (const int4*)dst_gc, (const int4*)dst_cc, (const int4*)dst_cg, (const int4*)dst_gg);

    const int NB = (NDEG + 1023) / 1024;
    scan_part1<<<NB, 1024>>>(deg, bsum, NDEG);          // also writes g_inv
    exscan_small<<<1, 1024>>>(bsum, bscan, NB);
    scan_part3<<<NB, 1024>>>(deg, bscan, rp, NDEG);     // also seeds g_cur

    fill_csr_all<<<(QALL + 255) / 256, 256>>>(
        (const int4*)src_gc, (const int4*)dst_gc, (const int4*)src_cc, (const int4*)dst_cc,
        (const int4*)src_cg, (const int4*)dst_cg, (const int4*)src_gg, (const int4*)dst_gg);

    const int nCellBlocks = (NCn + TM - 1) / TM;   // 1563
    const int nGeneBlocks = (NGn + TM - 1) / TM;   // 125

    auto make_sides = [&](const __half* hc, const __half* hg, void* oc, void* og,
                          Side& cs, Side& gs) {
        cs.rpA = rp + OFF_GC; cs.rpB = rp + OFF_CC;
        cs.hA = hg; cs.invA = inv + OFF_GC;
        cs.hB = hc; cs.invB = inv + OFF_CC;
        cs.WAhi = Whi + 0 * 16384; cs.WAlo = Wlo + 0 * 16384;
        cs.WBhi = Whi + 1 * 16384; cs.WBlo = Wlo + 1 * 16384;
        cs.bias = b_cell; cs.lns = ln_s_cell; cs.lnb = ln_b_cell;
        cs.out = oc; cs.n = NCn;

        gs.rpA = rp + OFF_CG; gs.rpB = rp + OFF_GG;
        gs.hA = hc; gs.invA = inv + OFF_CG;
        gs.hB = hg; gs.invB = inv + OFF_GG;
        gs.WAhi = Whi + 2 * 16384; gs.WAlo = Wlo + 2 * 16384;
        gs.WBhi = Whi + 3 * 16384; gs.WBlo = Wlo + 3 * 16384;
        gs.bias = b_gene; gs.lns = ln_s_gene; gs.lnb = ln_b_gene;
        gs.out = og; gs.n = NGn;
    };

    {
        Side cs, gs;
        make_sides(h16c, h16g, m16c, m16g, cs, gs);
        fused_layer<true><<<nGeneBlocks + nCellBlocks, 256, FUSED_SMEM>>>(
            cs, gs, col, nGeneBlocks);
    }
    {
        Side cs, gs;
        make_sides(m16c, m16g, out, out + (size_t)NCn * 128, cs, gs);
        fused_layer<false><<<nGeneBlocks + nCellBlocks, 256, FUSED_SMEM>>>(
            cs, gs, col, nGeneBlocks);
    }

    (void)in_sizes; (void)n_in; (void)out_size;
}

// round 14
// speedup vs baseline: 1.0917x; 1.0917x over previous
#include <cuda_runtime.h>
#include <cuda_bf16.h>
#include <cuda_fp16.h>
#include <cstdint>

// ---------------------------------------------------------------------------
// HiddenRRGCN round 14: revert gather to the proven 4-edge chunk (R12 inner
// loop; R13's 8-chunk broke the register/occupancy budget). Keeps the zero_i
// fold into convert_h_all. Otherwise identical to the 514.8 us R12 kernel.
// ---------------------------------------------------------------------------

static constexpr int NCn = 100000;
static constexpr int NGn = 8000;
static constexpr int E_CG = 1500000;
static constexpr int E_GC = 1500000;
static constexpr int E_CC = 1000000;
static constexpr int E_GG = 200000;
static constexpr int NDEG = 2 * NCn + 2 * NGn;
static constexpr int E_ALL = E_CG + E_GC + E_CC + E_GG;

static constexpr int OFF_GC = 0;
static constexpr int OFF_CC = NCn;
static constexpr int OFF_CG = 2 * NCn;
static constexpr int OFF_GG = 2 * NCn + NGn;

static constexpr int Q1 = E_GC / 4;
static constexpr int Q2 = Q1 + E_CC / 4;
static constexpr int Q3 = Q2 + E_CG / 4;
static constexpr int QALL = E_ALL / 4;

// ---- static scratch -------------------------------------------------------
__device__ int   g_deg[NDEG];
__device__ float g_inv[NDEG];
__device__ int   g_cur[NDEG];
__device__ int   g_rp[NDEG + 1];
__device__ int   g_col[E_ALL];
__device__ int   g_bsum[256];
__device__ int   g_bscan[257];
__device__ __align__(16) __half g_h16c[(size_t)NCn * 128];
__device__ __align__(16) __half g_h16g[(size_t)NGn * 128];
__device__ __align__(16) __half g_m16c[(size_t)NCn * 128];
__device__ __align__(16) __half g_m16g[(size_t)NGn * 128];
__device__ __align__(16) __nv_bfloat16 g_Whi[4][128 * 128];  // gc, cc, cg, gg
__device__ __align__(16) __nv_bfloat16 g_Wlo[4][128 * 128];

// ---------------------------------------------------------------------------
// convert fp32 features -> fp16 tables; ALSO zeroes g_deg (no dependency)
__global__ void convert_h_all(const float4* __restrict__ hc, const float4* __restrict__ hg) {
    int i = blockIdx.x * blockDim.x + threadIdx.x;
    const int NC4 = NCn * 32;
    const int NG4 = NGn * 32;
    if (i < NDEG) g_deg[i] = 0;
    if (i < NC4) {
        float4 v = __ldg(hc + i);
        __half2 a = __floats2half2_rn(v.x, v.y);
        __half2 b = __floats2half2_rn(v.z, v.w);
        reinterpret_cast<uint2*>(g_h16c)[i] = make_uint2(
            *reinterpret_cast<uint32_t*>(&a), *reinterpret_cast<uint32_t*>(&b));
    } else if (i < NC4 + NG4) {
        int j = i - NC4;
        float4 v = __ldg(hg + j);
        __half2 a = __floats2half2_rn(v.x, v.y);
        __half2 b = __floats2half2_rn(v.z, v.w);
        reinterpret_cast<uint2*>(g_h16g)[j] = make_uint2(
            *reinterpret_cast<uint32_t*>(&a), *reinterpret_cast<uint32_t*>(&b));
    }
}

__global__ void count_deg_all(const int4* __restrict__ dst_gc, const int4* __restrict__ dst_cc,
                              const int4* __restrict__ dst_cg, const int4* __restrict__ dst_gg) {
    int i = blockIdx.x * blockDim.x + threadIdx.x;
    if (i >= QALL) return;
    int4 d; int off;
    if (i < Q1)      { d = __ldg(dst_gc + i);      off = OFF_GC; }
    else if (i < Q2) { d = __ldg(dst_cc + i - Q1); off = OFF_CC; }
    else if (i < Q3) { d = __ldg(dst_cg + i - Q2); off = OFF_CG; }
    else             { d = __ldg(dst_gg + i - Q3); off = OFF_GG; }
    atomicAdd(&g_deg[off + d.x], 1);
    atomicAdd(&g_deg[off + d.y], 1);
    atomicAdd(&g_deg[off + d.z], 1);
    atomicAdd(&g_deg[off + d.w], 1);
}

__global__ void convert_w_all(const float* __restrict__ W0, const float* __restrict__ W1,
                              const float* __restrict__ W2, const float* __restrict__ W3) {
    int i = blockIdx.x * blockDim.x + threadIdx.x;
    if (i >= 4 * 16384) return;
    int m = i >> 14;
    int j = i & 16383;
    const float* W = (m == 0) ? W0 : (m == 1) ? W1 : (m == 2) ? W2 : W3;
    float v = W[j];
    __nv_bfloat16 h = __float2bfloat16_rn(v);
    g_Whi[m][j] = h;
    g_Wlo[m][j] = __float2bfloat16_rn(v - __bfloat162float(h));
}

__global__ void scan_part1(const int* __restrict__ in, int* __restrict__ bsum, int n) {
    __shared__ int ws[32];
    int tid = threadIdx.x;
    int i = blockIdx.x * 1024 + tid;
    int v = (i < n) ? in[i] : 0;
    if (i < n) g_inv[i] = 1.0f / (float)(v > 0 ? v : 1);
    int x = v;
#pragma unroll
    for (int o = 16; o > 0; o >>= 1) x += __shfl_xor_sync(0xffffffffu, x, o);
    if ((tid & 31) == 0) ws[tid >> 5] = x;
    __syncthreads();
    if (tid < 32) {
        int s = ws[tid];
#pragma unroll
        for (int o = 16; o > 0; o >>= 1) s += __shfl_xor_sync(0xffffffffu, s, o);
        if (tid == 0) bsum[blockIdx.x] = s;
    }
}

__global__ void exscan_small(const int* __restrict__ in, int* __restrict__ out, int n) {
    __shared__ int ws[32];
    int tid = threadIdx.x;
    int v = (tid < n) ? in[tid] : 0;
    int x = v;
#pragma unroll
    for (int o = 1; o < 32; o <<= 1) {
        int t = __shfl_up_sync(0xffffffffu, x, o);
        if ((tid & 31) >= o) x += t;
    }
    if ((tid & 31) == 31) ws[tid >> 5] = x;
    __syncthreads();
    if (tid < 32) {
        int s = ws[tid];
#pragma unroll
        for (int o = 1; o < 32; o <<= 1) {
            int t = __shfl_up_sync(0xffffffffu, s, o);
            if (tid >= o) s += t;
        }
        ws[tid] = s;
    }
    __syncthreads();
    int woff = (tid >= 32) ? ws[(tid >> 5) - 1] : 0;
    if (tid < n) out[tid] = x - v + woff;
    if (tid == n - 1) out[n] = x + woff;
}

__global__ void scan_part3(const int* __restrict__ in, const int* __restrict__ boff,
                           int* __restrict__ out, int n) {
    __shared__ int ws[32];
    int tid = threadIdx.x;
    int i = blockIdx.x * 1024 + tid;
    int v = (i < n) ? in[i] : 0;
    int x = v;
#pragma unroll
    for (int o = 1; o < 32; o <<= 1) {
        int t = __shfl_up_sync(0xffffffffu, x, o);
        if ((tid & 31) >= o) x += t;
    }
    if ((tid & 31) == 31) ws[tid >> 5] = x;
    __syncthreads();
    if (tid < 32) {
        int s = ws[tid];
#pragma unroll
        for (int o = 1; o < 32; o <<= 1) {
            int t = __shfl_up_sync(0xffffffffu, s, o);
            if (tid >= o) s += t;
        }
        ws[tid] = s;
    }
    __syncthreads();
    int woff = ((tid >> 5) > 0) ? ws[(tid >> 5) - 1] : 0;
    int excl = x - v + woff + boff[blockIdx.x];
    if (i < n) {
        out[i] = excl;
        g_cur[i] = excl;
    }
    if (i == n - 1) out[n] = excl + v;
}

__global__ void fill_csr_all(const int4* __restrict__ src_gc, const int4* __restrict__ dst_gc,
                             const int4* __restrict__ src_cc, const int4* __restrict__ dst_cc,
                             const int4* __restrict__ src_cg, const int4* __restrict__ dst_cg,
                             const int4* __restrict__ src_gg, const int4* __restrict__ dst_gg) {
    int i = blockIdx.x * blockDim.x + threadIdx.x;
    if (i >= QALL) return;
    int4 s, d; int off;
    if (i < Q1)      { s = __ldg(src_gc + i);      d = __ldg(dst_gc + i);      off = OFF_GC; }
    else if (i < Q2) { s = __ldg(src_cc + i - Q1); d = __ldg(dst_cc + i - Q1); off = OFF_CC; }
    else if (i < Q3) { s = __ldg(src_cg + i - Q2); d = __ldg(dst_cg + i - Q2); off = OFF_CG; }
    else             { s = __ldg(src_gg + i - Q3); d = __ldg(dst_gg + i - Q3); off = OFF_GG; }
    int p0 = atomicAdd(&g_cur[off + d.x], 1);
    int p1 = atomicAdd(&g_cur[off + d.y], 1);
    int p2 = atomicAdd(&g_cur[off + d.z], 1);
    int p3 = atomicAdd(&g_cur[off + d.w], 1);
    g_col[p0] = s.x;
    g_col[p1] = s.y;
    g_col[p2] = s.z;
    g_col[p3] = s.w;
}

// ---------------------------------------------------------------------------
__device__ __forceinline__ uint32_t s2u(const void* p) {
    return (uint32_t)__cvta_generic_to_shared(p);
}

__device__ __forceinline__ void ldsm_x4(uint32_t addr, uint32_t& r0, uint32_t& r1,
                                        uint32_t& r2, uint32_t& r3) {
    asm volatile("ldmatrix.sync.aligned.m8n8.x4.shared.b16 {%0,%1,%2,%3}, [%4];"
                 : "=r"(r0), "=r"(r1), "=r"(r2), "=r"(r3) : "r"(addr));
}

__device__ __forceinline__ void ldsm_x2t(uint32_t addr, uint32_t& r0, uint32_t& r1) {
    asm volatile("ldmatrix.sync.aligned.m8n8.x2.trans.shared.b16 {%0,%1}, [%2];"
                 : "=r"(r0), "=r"(r1) : "r"(addr));
}

__device__ __forceinline__ void mma_bf16(float* c, const uint32_t* a, const uint32_t* b) {
    asm volatile(
        "mma.sync.aligned.m16n8k16.row.col.f32.bf16.bf16.f32 "
        "{%0,%1,%2,%3}, {%4,%5,%6,%7}, {%8,%9}, {%0,%1,%2,%3};"
        : "+f"(c[0]), "+f"(c[1]), "+f"(c[2]), "+f"(c[3])
        : "r"(a[0]), "r"(a[1]), "r"(a[2]), "r"(a[3]), "r"(b[0]), "r"(b[1]));
}

__device__ __forceinline__ void acc_h4(float4& a, uint2 v) {
    float2 p = __half22float2(*reinterpret_cast<__half2*>(&v.x));
    float2 q = __half22float2(*reinterpret_cast<__half2*>(&v.y));
    a.x += p.x; a.y += p.y; a.z += q.x; a.w += q.y;
}

struct Side {
    const int* rpA; const int* rpB;
    const __half* hA; const float* invA;
    const __half* hB; const float* invB;
    const __nv_bfloat16 *WAhi, *WAlo, *WBhi, *WBlo;
    const float *bias, *lns, *lnb;
    void* out;
    int n;
};

static constexpr int TM = 64;
static constexpr int XSTR = 136;
static constexpr int WSTR = 136;
static constexpr int FUSED_SMEM =
    (TM * XSTR * 2) * 2 +
    (64 * WSTR * 2) * 2 +
    (TM * 4 * 4) * 2 +
    TM * 2 * 4;

template <bool OUT_HALF>
__global__ void __launch_bounds__(256, 3)
fused_layer(const Side cs, const Side gs, const int* __restrict__ colAll, int nGeneBlocks) {
    constexpr int NT = 4;
    constexpr int WARPS_N = 4;

    extern __shared__ char smem[];
    __nv_bfloat16* Xhi = reinterpret_cast<__nv_bfloat16*>(smem);
    __nv_bfloat16* Xlo = Xhi + TM * XSTR;
    __nv_bfloat16* Whs = Xlo + TM * XSTR;
    __nv_bfloat16* Wls = Whs + 64 * WSTR;
    float* spsum = reinterpret_cast<float*>(Wls + 64 * WSTR);
    float* spsq  = spsum + TM * WARPS_N;
    float* stats = spsq + TM * WARPS_N;

    const bool isGene = (int)blockIdx.x < nGeneBlocks;
    const Side* S = isGene ? &gs : &cs;
    const int blk = isGene ? blockIdx.x : (blockIdx.x - nGeneBlocks);
    const int row0 = blk * TM;
    const int n = S->n;

    const int tid = threadIdx.x;
    const int lane = tid & 31;
    const int wid = tid >> 5;
    const int warp_m = (wid & 1) * 32;
    const int nwid = wid >> 1;
    const int warp_n = nwid * 32;

    uint32_t xhi_base[2], xlo_base[2];
#pragma unroll
    for (int mi = 0; mi < 2; ++mi) {
        int row = warp_m + mi * 16 + (lane & 15);
        int koff = (lane >> 4) << 3;
        xhi_base[mi] = s2u(Xhi) + (row * XSTR + koff) * 2;
        xlo_base[mi] = s2u(Xlo) + (row * XSTR + koff) * 2;
    }
    uint32_t wh_base[NT], wl_base[NT];
#pragma unroll
    for (int ni = 0; ni < NT; ++ni) {
        int off = ((lane & 15) * WSTR + warp_n + ni * 8) * 2;
        wh_base[ni] = s2u(Whs) + off;
        wl_base[ni] = s2u(Wls) + off;
    }

    float acc[2][NT][4];
#pragma unroll
    for (int mi = 0; mi < 2; ++mi)
#pragma unroll
        for (int ni = 0; ni < NT; ++ni)
#pragma unroll
            for (int j = 0; j < 4; ++j) acc[mi][ni][j] = 0.f;

#pragma unroll
    for (int half = 0; half < 2; ++half) {
        const int* rp = half ? S->rpB : S->rpA;
        const uint2* hp = reinterpret_cast<const uint2*>(half ? S->hB : S->hA);
        const float* invp = half ? S->invB : S->invA;
        const __nv_bfloat16* Whig = half ? S->WBhi : S->WAhi;
        const __nv_bfloat16* Wlog = half ? S->WBlo : S->WAlo;

        __syncthreads();   // previous half's X reads complete

        // ---- aggregation: predicated chunks of 4, cols software-pipelined ----
        for (int r = wid; r < TM; r += 8) {
            int row = row0 + r;
            float4 a0 = make_float4(0.f, 0.f, 0.f, 0.f);
            float4 a1 = a0, a2 = a0, a3 = a0;
            float sc = 0.f;
            if (row < n) {
                int e = __ldg(rp + row);
                const int eEnd = __ldg(rp + row + 1);
                sc = __ldg(invp + row);
                if (e < eEnd) {
                    const int last = eEnd - 1;
                    int s0 = __ldg(colAll + e);
                    int s1 = __ldg(colAll + min(e + 1, last));
                    int s2 = __ldg(colAll + min(e + 2, last));
                    int s3 = __ldg(colAll + min(e + 3, last));
                    while (e < eEnd) {
                        const int en = e + 4;
                        uint2 z = make_uint2(0u, 0u);
                        uint2 v0 = __ldg(hp + (size_t)s0 * 32 + lane);
                        uint2 v1 = (e + 1 < eEnd) ? __ldg(hp + (size_t)s1 * 32 + lane) : z;
                        uint2 v2 = (e + 2 < eEnd) ? __ldg(hp + (size_t)s2 * 32 + lane) : z;
                        uint2 v3 = (e + 3 < eEnd) ? __ldg(hp + (size_t)s3 * 32 + lane) : z;
                        if (en < eEnd) {
                            s0 = __ldg(colAll + en);
                            s1 = __ldg(colAll + min(en + 1, last));
                            s2 = __ldg(colAll + min(en + 2, last));
                            s3 = __ldg(colAll + min(en + 3, last));
                        }
                        acc_h4(a0, v0);
                        acc_h4(a1, v1);
                        acc_h4(a2, v2);
                        acc_h4(a3, v3);
                        e = en;
                    }
                }
            }
            float vv[4] = {(a0.x + a1.x + a2.x + a3.x) * sc,
                           (a0.y + a1.y + a2.y + a3.y) * sc,
                           (a0.z + a1.z + a2.z + a3.z) * sc,
                           (a0.w + a1.w + a2.w + a3.w) * sc};
            __nv_bfloat16 hi4[4], lo4[4];
#pragma unroll
            for (int q = 0; q < 4; ++q) {
                __nv_bfloat16 h = __float2bfloat16_rn(vv[q]);
                hi4[q] = h;
                lo4[q] = __float2bfloat16_rn(vv[q] - __bfloat162float(h));
            }
            int xo = r * XSTR + lane * 4;
            *reinterpret_cast<uint2*>(Xhi + xo) = *reinterpret_cast<uint2*>(hi4);
            *reinterpret_cast<uint2*>(Xlo + xo) = *reinterpret_cast<uint2*>(lo4);
        }

        // ---- GEMM: 2 W tiles of 64 K-rows ----
#pragma unroll
        for (int kt2 = 0; kt2 < 2; ++kt2) {
            const __nv_bfloat16* Wghi = Whig + kt2 * 64 * 128;
            const __nv_bfloat16* Wglo = Wlog + kt2 * 64 * 128;
            __syncthreads();
#pragma unroll
            for (int c4 = 0; c4 < 4; ++c4) {
                int c = tid + c4 * 256;
                int wr = c >> 4;
                int wc = (c & 15) * 8;
                *reinterpret_cast<uint4*>(Whs + wr * WSTR + wc) =
                    __ldg(reinterpret_cast<const uint4*>(Wghi + wr * 128 + wc));
                *reinterpret_cast<uint4*>(Wls + wr * WSTR + wc) =
                    __ldg(reinterpret_cast<const uint4*>(Wglo + wr * 128 + wc));
            }
            __syncthreads();

#pragma unroll
            for (int ks = 0; ks < 4; ++ks) {
                int k0 = kt2 * 64 + ks * 16;
                uint32_t ah[2][4], al[2][4];
#pragma unroll
                for (int mi = 0; mi < 2; ++mi) {
                    ldsm_x4(xhi_base[mi] + k0 * 2, ah[mi][0], ah[mi][1], ah[mi][2], ah[mi][3]);
                    ldsm_x4(xlo_base[mi] + k0 * 2, al[mi][0], al[mi][1], al[mi][2], al[mi][3]);
                }
#pragma unroll
                for (int ni = 0; ni < NT; ++ni) {
                    uint32_t bh[2], bl[2];
                    ldsm_x2t(wh_base[ni] + (ks * 16) * WSTR * 2, bh[0], bh[1]);
                    ldsm_x2t(wl_base[ni] + (ks * 16) * WSTR * 2, bl[0], bl[1]);
#pragma unroll
                    for (int mi = 0; mi < 2; ++mi) {
                        mma_bf16(acc[mi][ni], ah[mi], bh);
                        mma_bf16(acc[mi][ni], ah[mi], bl);
                        mma_bf16(acc[mi][ni], al[mi], bh);
                    }
                }
            }
        }
    }

    // ---- epilogue ----
    const float* bias = S->bias;
    const float* lns = S->lns;
    const float* lnb = S->lnb;

    float2 bias2[NT], lns2[NT], lnb2[NT];
#pragma unroll
    for (int ni = 0; ni < NT; ++ni) {
        int col = warp_n + ni * 8 + (lane & 3) * 2;
        bias2[ni] = *reinterpret_cast<const float2*>(bias + col);
        lns2[ni] = *reinterpret_cast<const float2*>(lns + col);
        lnb2[ni] = *reinterpret_cast<const float2*>(lnb + col);
    }

#pragma unroll
    for (int mi = 0; mi < 2; ++mi)
#pragma unroll
        for (int rh = 0; rh < 2; ++rh) {
            float s = 0.f, q = 0.f;
#pragma unroll
            for (int ni = 0; ni < NT; ++ni) {
                float v0 = acc[mi][ni][rh * 2 + 0] + bias2[ni].x;
                float v1 = acc[mi][ni][rh * 2 + 1] + bias2[ni].y;
                v0 = (v0 >= 0.f) ? v0 : 0.05f * v0;
                v1 = (v1 >= 0.f) ? v1 : 0.05f * v1;
                acc[mi][ni][rh * 2 + 0] = v0;
                acc[mi][ni][rh * 2 + 1] = v1;
                s += v0 + v1;
                q += v0 * v0 + v1 * v1;
            }
#pragma unroll
            for (int o = 1; o < 4; o <<= 1) {
                s += __shfl_xor_sync(0xffffffffu, s, o);
                q += __shfl_xor_sync(0xffffffffu, q, o);
            }
            if ((lane & 3) == 0) {
                int rl = warp_m + mi * 16 + (lane >> 2) + rh * 8;
                spsum[rl * WARPS_N + nwid] = s;
                spsq[rl * WARPS_N + nwid] = q;
            }
        }
    __syncthreads();

    if (tid < TM) {
        float s = 0.f, q = 0.f;
#pragma unroll
        for (int i = 0; i < WARPS_N; ++i) {
            s += spsum[tid * WARPS_N + i];
            q += spsq[tid * WARPS_N + i];
        }
        float mean = s * (1.f / 128.f);
        float var = q * (1.f / 128.f) - mean * mean;
        stats[tid * 2] = mean;
        stats[tid * 2 + 1] = rsqrtf(var + 1e-5f);
    }
    __syncthreads();

#pragma unroll
    for (int mi = 0; mi < 2; ++mi)
#pragma unroll
        for (int rh = 0; rh < 2; ++rh) {
            int rl = warp_m + mi * 16 + (lane >> 2) + rh * 8;
            int row = row0 + rl;
            if (row < n) {
                float mean = stats[rl * 2];
                float rstd = stats[rl * 2 + 1];
#pragma unroll
                for (int ni = 0; ni < NT; ++ni) {
                    int col = warp_n + ni * 8 + (lane & 3) * 2;
                    float y0 = (acc[mi][ni][rh * 2 + 0] - mean) * rstd * lns2[ni].x + lnb2[ni].x;
                    float y1 = (acc[mi][ni][rh * 2 + 1] - mean) * rstd * lns2[ni].y + lnb2[ni].y;
                    if (OUT_HALF) {
                        __half2 y2 = __floats2half2_rn(y0, y1);
                        *reinterpret_cast<__half2*>(
                            reinterpret_cast<__half*>(S->out) + (size_t)row * 128 + col) = y2;
                    } else {
                        *reinterpret_cast<float2*>(
                            reinterpret_cast<float*>(S->out) + (size_t)row * 128 + col) =
                            make_float2(y0, y1);
                    }
                }
            }
        }
}

// ---------------------------------------------------------------------------
extern "C" void kernel_launch(void* const* d_in, const int* in_sizes, int n_in,
                              void* d_out, int out_size) {
    const float* h_cell = (const float*)d_in[0];
    const float* h_gene = (const float*)d_in[1];
    const int* src_cg = (const int*)d_in[2];
    const int* dst_cg = (const int*)d_in[3];
    const int* src_gc = (const int*)d_in[4];
    const int* dst_gc = (const int*)d_in[5];
    const int* src_cc = (const int*)d_in[6];
    const int* dst_cc = (const int*)d_in[7];
    const int* src_gg = (const int*)d_in[8];
    const int* dst_gg = (const int*)d_in[9];
    const float* W_cg = (const float*)d_in[10];
    const float* W_gc = (const float*)d_in[11];
    const float* W_cc = (const float*)d_in[12];
    const float* W_gg = (const float*)d_in[13];
    const float* b_cell = (const float*)d_in[14];
    const float* b_gene = (const float*)d_in[15];
    const float* ln_s_cell = (const float*)d_in[16];
    const float* ln_b_cell = (const float*)d_in[17];
    const float* ln_s_gene = (const float*)d_in[18];
    const float* ln_b_gene = (const float*)d_in[19];
    float* out = (float*)d_out;

    int *rp, *bsum, *bscan, *col, *deg;
    float *inv;
    __half *h16c, *h16g, *m16c, *m16g;
    __nv_bfloat16 *Whi, *Wlo;
    cudaGetSymbolAddress((void**)&deg, g_deg);
    cudaGetSymbolAddress((void**)&rp, g_rp);
    cudaGetSymbolAddress((void**)&col, g_col);
    cudaGetSymbolAddress((void**)&bsum, g_bsum);
    cudaGetSymbolAddress((void**)&bscan, g_bscan);
    cudaGetSymbolAddress((void**)&inv, g_inv);
    cudaGetSymbolAddress((void**)&h16c, g_h16c);
    cudaGetSymbolAddress((void**)&h16g, g_h16g);
    cudaGetSymbolAddress((void**)&m16c, g_m16c);
    cudaGetSymbolAddress((void**)&m16g, g_m16g);
    cudaGetSymbolAddress((void**)&Whi, g_Whi);
    cudaGetSymbolAddress((void**)&Wlo, g_Wlo);

    cudaFuncSetAttribute(fused_layer<true>, cudaFuncAttributeMaxDynamicSharedMemorySize, FUSED_SMEM);
    cudaFuncSetAttribute(fused_layer<false>, cudaFuncAttributeMaxDynamicSharedMemorySize, FUSED_SMEM);

    // ---- setup ----
    convert_w_all<<<(4 * 16384 + 255) / 256, 256>>>(W_gc, W_cc, W_cg, W_gg);
    convert_h_all<<<((NCn + NGn) * 32 + 255) / 256, 256>>>(
        (const float4*)h_cell, (const float4*)h_gene);   // also zeroes g_deg
    count_deg_all<<<(QALL + 255) / 256, 256>>>(
        (const int4*)dst_gc, (const int4*)dst_cc, (const int4*)dst_cg, (const int4*)dst_gg);

    const int NB = (NDEG + 1023) / 1024;
    scan_part1<<<NB, 1024>>>(deg, bsum, NDEG);          // also writes g_inv
    exscan_small<<<1, 1024>>>(bsum, bscan, NB);
    scan_part3<<<NB, 1024>>>(deg, bscan, rp, NDEG);     // also seeds g_cur

    fill_csr_all<<<(QALL + 255) / 256, 256>>>(
        (const int4*)src_gc, (const int4*)dst_gc, (const int4*)src_cc, (const int4*)dst_cc,
        (const int4*)src_cg, (const int4*)dst_cg, (const int4*)src_gg, (const int4*)dst_gg);

    const int nCellBlocks = (NCn + TM - 1) / TM;   // 1563
    const int nGeneBlocks = (NGn + TM - 1) / TM;   // 125

    auto make_sides = [&](const __half* hc, const __half* hg, void* oc, void* og,
                          Side& cs, Side& gs) {
        cs.rpA = rp + OFF_GC; cs.rpB = rp + OFF_CC;
        cs.hA = hg; cs.invA = inv + OFF_GC;
        cs.hB = hc; cs.invB = inv + OFF_CC;
        cs.WAhi = Whi + 0 * 16384; cs.WAlo = Wlo + 0 * 16384;
        cs.WBhi = Whi + 1 * 16384; cs.WBlo = Wlo + 1 * 16384;
        cs.bias = b_cell; cs.lns = ln_s_cell; cs.lnb = ln_b_cell;
        cs.out = oc; cs.n = NCn;

        gs.rpA = rp + OFF_CG; gs.rpB = rp + OFF_GG;
        gs.hA = hc; gs.invA = inv + OFF_CG;
        gs.hB = hg; gs.invB = inv + OFF_GG;
        gs.WAhi = Whi + 2 * 16384; gs.WAlo = Wlo + 2 * 16384;
        gs.WBhi = Whi + 3 * 16384; gs.WBlo = Wlo + 3 * 16384;
        gs.bias = b_gene; gs.lns = ln_s_gene; gs.lnb = ln_b_gene;
        gs.out = og; gs.n = NGn;
    };

    {
        Side cs, gs;
        make_sides(h16c, h16g, m16c, m16g, cs, gs);
        fused_layer<true><<<nGeneBlocks + nCellBlocks, 256, FUSED_SMEM>>>(
            cs, gs, col, nGeneBlocks);
    }
    {
        Side cs, gs;
        make_sides(m16c, m16g, out, out + (size_t)NCn * 128, cs, gs);
        fused_layer<false><<<nGeneBlocks + nCellBlocks, 256, FUSED_SMEM>>>(
            cs, gs, col, nGeneBlocks);
    }

    (void)in_sizes; (void)n_in; (void)out_size;
}

// round 15
// speedup vs baseline: 1.0956x; 1.0035x over previous
#include <cuda_runtime.h>
#include <cuda_bf16.h>
#include <cuda_fp16.h>
#include <cstdint>

// ---------------------------------------------------------------------------
// HiddenRRGCN round 15: R14 (512.2 us) + setup-chain trims:
//  - convert_w folded into convert_h (one prep kernel: W split + h->fp16 + deg=0)
//  - exscan_small dropped; scan_part3 self-computes its block offset from bsum
// Layer kernels byte-identical to R14.
// ---------------------------------------------------------------------------

static constexpr int NCn = 100000;
static constexpr int NGn = 8000;
static constexpr int E_CG = 1500000;
static constexpr int E_GC = 1500000;
static constexpr int E_CC = 1000000;
static constexpr int E_GG = 200000;
static constexpr int NDEG = 2 * NCn + 2 * NGn;
static constexpr int E_ALL = E_CG + E_GC + E_CC + E_GG;

static constexpr int OFF_GC = 0;
static constexpr int OFF_CC = NCn;
static constexpr int OFF_CG = 2 * NCn;
static constexpr int OFF_GG = 2 * NCn + NGn;

static constexpr int Q1 = E_GC / 4;
static constexpr int Q2 = Q1 + E_CC / 4;
static constexpr int Q3 = Q2 + E_CG / 4;
static constexpr int QALL = E_ALL / 4;

// ---- static scratch -------------------------------------------------------
__device__ int   g_deg[NDEG];
__device__ float g_inv[NDEG];
__device__ int   g_cur[NDEG];
__device__ int   g_rp[NDEG + 1];
__device__ int   g_col[E_ALL];
__device__ int   g_bsum[256];
__device__ __align__(16) __half g_h16c[(size_t)NCn * 128];
__device__ __align__(16) __half g_h16g[(size_t)NGn * 128];
__device__ __align__(16) __half g_m16c[(size_t)NCn * 128];
__device__ __align__(16) __half g_m16g[(size_t)NGn * 128];
__device__ __align__(16) __nv_bfloat16 g_Whi[4][128 * 128];  // gc, cc, cg, gg
__device__ __align__(16) __nv_bfloat16 g_Wlo[4][128 * 128];

// ---------------------------------------------------------------------------
// One prep kernel: W bf16 hi/lo split + features -> fp16 + zero g_deg.
// Range: [0, 64K) -> W elements (4 matrices); [64K, 64K+NC4+NG4) -> features.
static constexpr int WELEMS = 4 * 16384;   // 65536
__global__ void prep_all(const float* __restrict__ W0, const float* __restrict__ W1,
                         const float* __restrict__ W2, const float* __restrict__ W3,
                         const float4* __restrict__ hc, const float4* __restrict__ hg) {
    int i = blockIdx.x * blockDim.x + threadIdx.x;
    const int NC4 = NCn * 32;
    const int NG4 = NGn * 32;
    if (i < NDEG) g_deg[i] = 0;
    if (i < WELEMS) {
        int m = i >> 14;
        int j = i & 16383;
        const float* W = (m == 0) ? W0 : (m == 1) ? W1 : (m == 2) ? W2 : W3;
        float v = W[j];
        __nv_bfloat16 h = __float2bfloat16_rn(v);
        g_Whi[m][j] = h;
        g_Wlo[m][j] = __float2bfloat16_rn(v - __bfloat162float(h));
        return;
    }
    int k = i - WELEMS;
    if (k < NC4) {
        float4 v = __ldg(hc + k);
        __half2 a = __floats2half2_rn(v.x, v.y);
        __half2 b = __floats2half2_rn(v.z, v.w);
        reinterpret_cast<uint2*>(g_h16c)[k] = make_uint2(
            *reinterpret_cast<uint32_t*>(&a), *reinterpret_cast<uint32_t*>(&b));
    } else if (k < NC4 + NG4) {
        int j = k - NC4;
        float4 v = __ldg(hg + j);
        __half2 a = __floats2half2_rn(v.x, v.y);
        __half2 b = __floats2half2_rn(v.z, v.w);
        reinterpret_cast<uint2*>(g_h16g)[j] = make_uint2(
            *reinterpret_cast<uint32_t*>(&a), *reinterpret_cast<uint32_t*>(&b));
    }
}

__global__ void count_deg_all(const int4* __restrict__ dst_gc, const int4* __restrict__ dst_cc,
                              const int4* __restrict__ dst_cg, const int4* __restrict__ dst_gg) {
    int i = blockIdx.x * blockDim.x + threadIdx.x;
    if (i >= QALL) return;
    int4 d; int off;
    if (i < Q1)      { d = __ldg(dst_gc + i);      off = OFF_GC; }
    else if (i < Q2) { d = __ldg(dst_cc + i - Q1); off = OFF_CC; }
    else if (i < Q3) { d = __ldg(dst_cg + i - Q2); off = OFF_CG; }
    else             { d = __ldg(dst_gg + i - Q3); off = OFF_GG; }
    atomicAdd(&g_deg[off + d.x], 1);
    atomicAdd(&g_deg[off + d.y], 1);
    atomicAdd(&g_deg[off + d.z], 1);
    atomicAdd(&g_deg[off + d.w], 1);
}

// ---- scan pass 1: per-block sums (also emits inv-degree) ----
__global__ void scan_part1(const int* __restrict__ in, int* __restrict__ bsum, int n) {
    __shared__ int ws[32];
    int tid = threadIdx.x;
    int i = blockIdx.x * 1024 + tid;
    int v = (i < n) ? in[i] : 0;
    if (i < n) g_inv[i] = 1.0f / (float)(v > 0 ? v : 1);
    int x = v;
#pragma unroll
    for (int o = 16; o > 0; o >>= 1) x += __shfl_xor_sync(0xffffffffu, x, o);
    if ((tid & 31) == 0) ws[tid >> 5] = x;
    __syncthreads();
    if (tid < 32) {
        int s = ws[tid];
#pragma unroll
        for (int o = 16; o > 0; o >>= 1) s += __shfl_xor_sync(0xffffffffu, s, o);
        if (tid == 0) bsum[blockIdx.x] = s;
    }
}

// ---- scan pass 2: exclusive scan; each block sums bsum[0..bid) itself ----
__global__ void scan_part3(const int* __restrict__ in, const int* __restrict__ bsum,
                           int* __restrict__ out, int n, int nb) {
    __shared__ int ws[32];
    __shared__ int s_boff;
    int tid = threadIdx.x;
    int i = blockIdx.x * 1024 + tid;

    // block offset = sum of bsum[0..blockIdx.x): first warp reduces it
    if (tid < 32) {
        int acc = 0;
        for (int j = tid; j < blockIdx.x; j += 32) acc += __ldg(bsum + j);
#pragma unroll
        for (int o = 16; o > 0; o >>= 1) acc += __shfl_xor_sync(0xffffffffu, acc, o);
        if (tid == 0) s_boff = acc;
    }

    int v = (i < n) ? in[i] : 0;
    int x = v;
#pragma unroll
    for (int o = 1; o < 32; o <<= 1) {
        int t = __shfl_up_sync(0xffffffffu, x, o);
        if ((tid & 31) >= o) x += t;
    }
    if ((tid & 31) == 31) ws[tid >> 5] = x;
    __syncthreads();
    if (tid < 32) {
        int s = ws[tid];
#pragma unroll
        for (int o = 1; o < 32; o <<= 1) {
            int t = __shfl_up_sync(0xffffffffu, s, o);
            if (tid >= o) s += t;
        }
        ws[tid] = s;
    }
    __syncthreads();
    int woff = ((tid >> 5) > 0) ? ws[(tid >> 5) - 1] : 0;
    int excl = x - v + woff + s_boff;
    if (i < n) {
        out[i] = excl;
        g_cur[i] = excl;
    }
    if (i == n - 1) out[n] = excl + v;
    (void)nb;
}

__global__ void fill_csr_all(const int4* __restrict__ src_gc, const int4* __restrict__ dst_gc,
                             const int4* __restrict__ src_cc, const int4* __restrict__ dst_cc,
                             const int4* __restrict__ src_cg, const int4* __restrict__ dst_cg,
                             const int4* __restrict__ src_gg, const int4* __restrict__ dst_gg) {
    int i = blockIdx.x * blockDim.x + threadIdx.x;
    if (i >= QALL) return;
    int4 s, d; int off;
    if (i < Q1)      { s = __ldg(src_gc + i);      d = __ldg(dst_gc + i);      off = OFF_GC; }
    else if (i < Q2) { s = __ldg(src_cc + i - Q1); d = __ldg(dst_cc + i - Q1); off = OFF_CC; }
    else if (i < Q3) { s = __ldg(src_cg + i - Q2); d = __ldg(dst_cg + i - Q2); off = OFF_CG; }
    else             { s = __ldg(src_gg + i - Q3); d = __ldg(dst_gg + i - Q3); off = OFF_GG; }
    int p0 = atomicAdd(&g_cur[off + d.x], 1);
    int p1 = atomicAdd(&g_cur[off + d.y], 1);
    int p2 = atomicAdd(&g_cur[off + d.z], 1);
    int p3 = atomicAdd(&g_cur[off + d.w], 1);
    g_col[p0] = s.x;
    g_col[p1] = s.y;
    g_col[p2] = s.z;
    g_col[p3] = s.w;
}

// ---------------------------------------------------------------------------
__device__ __forceinline__ uint32_t s2u(const void* p) {
    return (uint32_t)__cvta_generic_to_shared(p);
}

__device__ __forceinline__ void ldsm_x4(uint32_t addr, uint32_t& r0, uint32_t& r1,
                                        uint32_t& r2, uint32_t& r3) {
    asm volatile("ldmatrix.sync.aligned.m8n8.x4.shared.b16 {%0,%1,%2,%3}, [%4];"
                 : "=r"(r0), "=r"(r1), "=r"(r2), "=r"(r3) : "r"(addr));
}

__device__ __forceinline__ void ldsm_x2t(uint32_t addr, uint32_t& r0, uint32_t& r1) {
    asm volatile("ldmatrix.sync.aligned.m8n8.x2.trans.shared.b16 {%0,%1}, [%2];"
                 : "=r"(r0), "=r"(r1) : "r"(addr));
}

__device__ __forceinline__ void mma_bf16(float* c, const uint32_t* a, const uint32_t* b) {
    asm volatile(
        "mma.sync.aligned.m16n8k16.row.col.f32.bf16.bf16.f32 "
        "{%0,%1,%2,%3}, {%4,%5,%6,%7}, {%8,%9}, {%0,%1,%2,%3};"
        : "+f"(c[0]), "+f"(c[1]), "+f"(c[2]), "+f"(c[3])
        : "r"(a[0]), "r"(a[1]), "r"(a[2]), "r"(a[3]), "r"(b[0]), "r"(b[1]));
}

__device__ __forceinline__ void acc_h4(float4& a, uint2 v) {
    float2 p = __half22float2(*reinterpret_cast<__half2*>(&v.x));
    float2 q = __half22float2(*reinterpret_cast<__half2*>(&v.y));
    a.x += p.x; a.y += p.y; a.z += q.x; a.w += q.y;
}

struct Side {
    const int* rpA; const int* rpB;
    const __half* hA; const float* invA;
    const __half* hB; const float* invB;
    const __nv_bfloat16 *WAhi, *WAlo, *WBhi, *WBlo;
    const float *bias, *lns, *lnb;
    void* out;
    int n;
};

static constexpr int TM = 64;
static constexpr int XSTR = 136;
static constexpr int WSTR = 136;
static constexpr int FUSED_SMEM =
    (TM * XSTR * 2) * 2 +
    (64 * WSTR * 2) * 2 +
    (TM * 4 * 4) * 2 +
    TM * 2 * 4;

template <bool OUT_HALF>
__global__ void __launch_bounds__(256, 3)
fused_layer(const Side cs, const Side gs, const int* __restrict__ colAll, int nGeneBlocks) {
    constexpr int NT = 4;
    constexpr int WARPS_N = 4;

    extern __shared__ char smem[];
    __nv_bfloat16* Xhi = reinterpret_cast<__nv_bfloat16*>(smem);
    __nv_bfloat16* Xlo = Xhi + TM * XSTR;
    __nv_bfloat16* Whs = Xlo + TM * XSTR;
    __nv_bfloat16* Wls = Whs + 64 * WSTR;
    float* spsum = reinterpret_cast<float*>(Wls + 64 * WSTR);
    float* spsq  = spsum + TM * WARPS_N;
    float* stats = spsq + TM * WARPS_N;

    const bool isGene = (int)blockIdx.x < nGeneBlocks;
    const Side* S = isGene ? &gs : &cs;
    const int blk = isGene ? blockIdx.x : (blockIdx.x - nGeneBlocks);
    const int row0 = blk * TM;
    const int n = S->n;

    const int tid = threadIdx.x;
    const int lane = tid & 31;
    const int wid = tid >> 5;
    const int warp_m = (wid & 1) * 32;
    const int nwid = wid >> 1;
    const int warp_n = nwid * 32;

    uint32_t xhi_base[2], xlo_base[2];
#pragma unroll
    for (int mi = 0; mi < 2; ++mi) {
        int row = warp_m + mi * 16 + (lane & 15);
        int koff = (lane >> 4) << 3;
        xhi_base[mi] = s2u(Xhi) + (row * XSTR + koff) * 2;
        xlo_base[mi] = s2u(Xlo) + (row * XSTR + koff) * 2;
    }
    uint32_t wh_base[NT], wl_base[NT];
#pragma unroll
    for (int ni = 0; ni < NT; ++ni) {
        int off = ((lane & 15) * WSTR + warp_n + ni * 8) * 2;
        wh_base[ni] = s2u(Whs) + off;
        wl_base[ni] = s2u(Wls) + off;
    }

    float acc[2][NT][4];
#pragma unroll
    for (int mi = 0; mi < 2; ++mi)
#pragma unroll
        for (int ni = 0; ni < NT; ++ni)
#pragma unroll
            for (int j = 0; j < 4; ++j) acc[mi][ni][j] = 0.f;

#pragma unroll
    for (int half = 0; half < 2; ++half) {
        const int* rp = half ? S->rpB : S->rpA;
        const uint2* hp = reinterpret_cast<const uint2*>(half ? S->hB : S->hA);
        const float* invp = half ? S->invB : S->invA;
        const __nv_bfloat16* Whig = half ? S->WBhi : S->WAhi;
        const __nv_bfloat16* Wlog = half ? S->WBlo : S->WAlo;

        __syncthreads();   // previous half's X reads complete

        // ---- aggregation: predicated chunks of 4, cols software-pipelined ----
        for (int r = wid; r < TM; r += 8) {
            int row = row0 + r;
            float4 a0 = make_float4(0.f, 0.f, 0.f, 0.f);
            float4 a1 = a0, a2 = a0, a3 = a0;
            float sc = 0.f;
            if (row < n) {
                int e = __ldg(rp + row);
                const int eEnd = __ldg(rp + row + 1);
                sc = __ldg(invp + row);
                if (e < eEnd) {
                    const int last = eEnd - 1;
                    int s0 = __ldg(colAll + e);
                    int s1 = __ldg(colAll + min(e + 1, last));
                    int s2 = __ldg(colAll + min(e + 2, last));
                    int s3 = __ldg(colAll + min(e + 3, last));
                    while (e < eEnd) {
                        const int en = e + 4;
                        uint2 z = make_uint2(0u, 0u);
                        uint2 v0 = __ldg(hp + (size_t)s0 * 32 + lane);
                        uint2 v1 = (e + 1 < eEnd) ? __ldg(hp + (size_t)s1 * 32 + lane) : z;
                        uint2 v2 = (e + 2 < eEnd) ? __ldg(hp + (size_t)s2 * 32 + lane) : z;
                        uint2 v3 = (e + 3 < eEnd) ? __ldg(hp + (size_t)s3 * 32 + lane) : z;
                        if (en < eEnd) {
                            s0 = __ldg(colAll + en);
                            s1 = __ldg(colAll + min(en + 1, last));
                            s2 = __ldg(colAll + min(en + 2, last));
                            s3 = __ldg(colAll + min(en + 3, last));
                        }
                        acc_h4(a0, v0);
                        acc_h4(a1, v1);
                        acc_h4(a2, v2);
                        acc_h4(a3, v3);
                        e = en;
                    }
                }
            }
            float vv[4] = {(a0.x + a1.x + a2.x + a3.x) * sc,
                           (a0.y + a1.y + a2.y + a3.y) * sc,
                           (a0.z + a1.z + a2.z + a3.z) * sc,
                           (a0.w + a1.w + a2.w + a3.w) * sc};
            __nv_bfloat16 hi4[4], lo4[4];
#pragma unroll
            for (int q = 0; q < 4; ++q) {
                __nv_bfloat16 h = __float2bfloat16_rn(vv[q]);
                hi4[q] = h;
                lo4[q] = __float2bfloat16_rn(vv[q] - __bfloat162float(h));
            }
            int xo = r * XSTR + lane * 4;
            *reinterpret_cast<uint2*>(Xhi + xo) = *reinterpret_cast<uint2*>(hi4);
            *reinterpret_cast<uint2*>(Xlo + xo) = *reinterpret_cast<uint2*>(lo4);
        }

        // ---- GEMM: 2 W tiles of 64 K-rows ----
#pragma unroll
        for (int kt2 = 0; kt2 < 2; ++kt2) {
            const __nv_bfloat16* Wghi = Whig + kt2 * 64 * 128;
            const __nv_bfloat16* Wglo = Wlog + kt2 * 64 * 128;
            __syncthreads();
#pragma unroll
            for (int c4 = 0; c4 < 4; ++c4) {
                int c = tid + c4 * 256;
                int wr = c >> 4;
                int wc = (c & 15) * 8;
                *reinterpret_cast<uint4*>(Whs + wr * WSTR + wc) =
                    __ldg(reinterpret_cast<const uint4*>(Wghi + wr * 128 + wc));
                *reinterpret_cast<uint4*>(Wls + wr * WSTR + wc) =
                    __ldg(reinterpret_cast<const uint4*>(Wglo + wr * 128 + wc));
            }
            __syncthreads();

#pragma unroll
            for (int ks = 0; ks < 4; ++ks) {
                int k0 = kt2 * 64 + ks * 16;
                uint32_t ah[2][4], al[2][4];
#pragma unroll
                for (int mi = 0; mi < 2; ++mi) {
                    ldsm_x4(xhi_base[mi] + k0 * 2, ah[mi][0], ah[mi][1], ah[mi][2], ah[mi][3]);
                    ldsm_x4(xlo_base[mi] + k0 * 2, al[mi][0], al[mi][1], al[mi][2], al[mi][3]);
                }
#pragma unroll
                for (int ni = 0; ni < NT; ++ni) {
                    uint32_t bh[2], bl[2];
                    ldsm_x2t(wh_base[ni] + (ks * 16) * WSTR * 2, bh[0], bh[1]);
                    ldsm_x2t(wl_base[ni] + (ks * 16) * WSTR * 2, bl[0], bl[1]);
#pragma unroll
                    for (int mi = 0; mi < 2; ++mi) {
                        mma_bf16(acc[mi][ni], ah[mi], bh);
                        mma_bf16(acc[mi][ni], ah[mi], bl);
                        mma_bf16(acc[mi][ni], al[mi], bh);
                    }
                }
            }
        }
    }

    // ---- epilogue ----
    const float* bias = S->bias;
    const float* lns = S->lns;
    const float* lnb = S->lnb;

    float2 bias2[NT], lns2[NT], lnb2[NT];
#pragma unroll
    for (int ni = 0; ni < NT; ++ni) {
        int col = warp_n + ni * 8 + (lane & 3) * 2;
        bias2[ni] = *reinterpret_cast<const float2*>(bias + col);
        lns2[ni] = *reinterpret_cast<const float2*>(lns + col);
        lnb2[ni] = *reinterpret_cast<const float2*>(lnb + col);
    }

#pragma unroll
    for (int mi = 0; mi < 2; ++mi)
#pragma unroll
        for (int rh = 0; rh < 2; ++rh) {
            float s = 0.f, q = 0.f;
#pragma unroll
            for (int ni = 0; ni < NT; ++ni) {
                float v0 = acc[mi][ni][rh * 2 + 0] + bias2[ni].x;
                float v1 = acc[mi][ni][rh * 2 + 1] + bias2[ni].y;
                v0 = (v0 >= 0.f) ? v0 : 0.05f * v0;
                v1 = (v1 >= 0.f) ? v1 : 0.05f * v1;
                acc[mi][ni][rh * 2 + 0] = v0;
                acc[mi][ni][rh * 2 + 1] = v1;
                s += v0 + v1;
                q += v0 * v0 + v1 * v1;
            }
#pragma unroll
            for (int o = 1; o < 4; o <<= 1) {
                s += __shfl_xor_sync(0xffffffffu, s, o);
                q += __shfl_xor_sync(0xffffffffu, q, o);
            }
            if ((lane & 3) == 0) {
                int rl = warp_m + mi * 16 + (lane >> 2) + rh * 8;
                spsum[rl * WARPS_N + nwid] = s;
                spsq[rl * WARPS_N + nwid] = q;
            }
        }
    __syncthreads();

    if (tid < TM) {
        float s = 0.f, q = 0.f;
#pragma unroll
        for (int i = 0; i < WARPS_N; ++i) {
            s += spsum[tid * WARPS_N + i];
            q += spsq[tid * WARPS_N + i];
        }
        float mean = s * (1.f / 128.f);
        float var = q * (1.f / 128.f) - mean * mean;
        stats[tid * 2] = mean;
        stats[tid * 2 + 1] = rsqrtf(var + 1e-5f);
    }
    __syncthreads();

#pragma unroll
    for (int mi = 0; mi < 2; ++mi)
#pragma unroll
        for (int rh = 0; rh < 2; ++rh) {
            int rl = warp_m + mi * 16 + (lane >> 2) + rh * 8;
            int row = row0 + rl;
            if (row < n) {
                float mean = stats[rl * 2];
                float rstd = stats[rl * 2 + 1];
#pragma unroll
                for (int ni = 0; ni < NT; ++ni) {
                    int col = warp_n + ni * 8 + (lane & 3) * 2;
                    float y0 = (acc[mi][ni][rh * 2 + 0] - mean) * rstd * lns2[ni].x + lnb2[ni].x;
                    float y1 = (acc[mi][ni][rh * 2 + 1] - mean) * rstd * lns2[ni].y + lnb2[ni].y;
                    if (OUT_HALF) {
                        __half2 y2 = __floats2half2_rn(y0, y1);
                        *reinterpret_cast<__half2*>(
                            reinterpret_cast<__half*>(S->out) + (size_t)row * 128 + col) = y2;
                    } else {
                        *reinterpret_cast<float2*>(
                            reinterpret_cast<float*>(S->out) + (size_t)row * 128 + col) =
                            make_float2(y0, y1);
                    }
                }
            }
        }
}

// ---------------------------------------------------------------------------
extern "C" void kernel_launch(void* const* d_in, const int* in_sizes, int n_in,
                              void* d_out, int out_size) {
    const float* h_cell = (const float*)d_in[0];
    const float* h_gene = (const float*)d_in[1];
    const int* src_cg = (const int*)d_in[2];
    const int* dst_cg = (const int*)d_in[3];
    const int* src_gc = (const int*)d_in[4];
    const int* dst_gc = (const int*)d_in[5];
    const int* src_cc = (const int*)d_in[6];
    const int* dst_cc = (const int*)d_in[7];
    const int* src_gg = (const int*)d_in[8];
    const int* dst_gg = (const int*)d_in[9];
    const float* W_cg = (const float*)d_in[10];
    const float* W_gc = (const float*)d_in[11];
    const float* W_cc = (const float*)d_in[12];
    const float* W_gg = (const float*)d_in[13];
    const float* b_cell = (const float*)d_in[14];
    const float* b_gene = (const float*)d_in[15];
    const float* ln_s_cell = (const float*)d_in[16];
    const float* ln_b_cell = (const float*)d_in[17];
    const float* ln_s_gene = (const float*)d_in[18];
    const float* ln_b_gene = (const float*)d_in[19];
    float* out = (float*)d_out;

    int *rp, *bsum, *col, *deg;
    float *inv;
    __half *h16c, *h16g, *m16c, *m16g;
    __nv_bfloat16 *Whi, *Wlo;
    cudaGetSymbolAddress((void**)&deg, g_deg);
    cudaGetSymbolAddress((void**)&rp, g_rp);
    cudaGetSymbolAddress((void**)&col, g_col);
    cudaGetSymbolAddress((void**)&bsum, g_bsum);
    cudaGetSymbolAddress((void**)&inv, g_inv);
    cudaGetSymbolAddress((void**)&h16c, g_h16c);
    cudaGetSymbolAddress((void**)&h16g, g_h16g);
    cudaGetSymbolAddress((void**)&m16c, g_m16c);
    cudaGetSymbolAddress((void**)&m16g, g_m16g);
    cudaGetSymbolAddress((void**)&Whi, g_Whi);
    cudaGetSymbolAddress((void**)&Wlo, g_Wlo);

    cudaFuncSetAttribute(fused_layer<true>, cudaFuncAttributeMaxDynamicSharedMemorySize, FUSED_SMEM);
    cudaFuncSetAttribute(fused_layer<false>, cudaFuncAttributeMaxDynamicSharedMemorySize, FUSED_SMEM);

    // ---- setup: one prep kernel (W split + h->fp16 + deg=0), then CSR ----
    const int PREP_N = 4 * 16384 + (NCn + NGn) * 32;
    prep_all<<<(PREP_N + 255) / 256, 256>>>(W_gc, W_cc, W_cg, W_gg,
                                            (const float4*)h_cell, (const float4*)h_gene);
    count_deg_all<<<(QALL + 255) / 256, 256>>>(
        (const int4*)dst_gc, (const int4*)dst_cc, (const int4*)dst_cg, (const int4*)dst_gg);

    const int NB = (NDEG + 1023) / 1024;   // 211
    scan_part1<<<NB, 1024>>>(deg, bsum, NDEG);              // also writes g_inv
    scan_part3<<<NB, 1024>>>(deg, bsum, rp, NDEG, NB);      // self-offsets; seeds g_cur

    fill_csr_all<<<(QALL + 255) / 256, 256>>>(
        (const int4*)src_gc, (const int4*)dst_gc, (const int4*)src_cc, (const int4*)dst_cc,
        (const int4*)src_cg, (const int4*)dst_cg, (const int4*)src_gg, (const int4*)dst_gg);

    const int nCellBlocks = (NCn + TM - 1) / TM;   // 1563
    const int nGeneBlocks = (NGn + TM - 1) / TM;   // 125

    auto make_sides = [&](const __half* hc, const __half* hg, void* oc, void* og,
                          Side& cs, Side& gs) {
        cs.rpA = rp + OFF_GC; cs.rpB = rp + OFF_CC;
        cs.hA = hg; cs.invA = inv + OFF_GC;
        cs.hB = hc; cs.invB = inv + OFF_CC;
        cs.WAhi = Whi + 0 * 16384; cs.WAlo = Wlo + 0 * 16384;
        cs.WBhi = Whi + 1 * 16384; cs.WBlo = Wlo + 1 * 16384;
        cs.bias = b_cell; cs.lns = ln_s_cell; cs.lnb = ln_b_cell;
        cs.out = oc; cs.n = NCn;

        gs.rpA = rp + OFF_CG; gs.rpB = rp + OFF_GG;
        gs.hA = hc; gs.invA = inv + OFF_CG;
        gs.hB = hg; gs.invB = inv + OFF_GG;
        gs.WAhi = Whi + 2 * 16384; gs.WAlo = Wlo + 2 * 16384;
        gs.WBhi = Whi + 3 * 16384; gs.WBlo = Wlo + 3 * 16384;
        gs.bias = b_gene; gs.lns = ln_s_gene; gs.lnb = ln_b_gene;
        gs.out = og; gs.n = NGn;
    };

    {
        Side cs, gs;
        make_sides(h16c, h16g, m16c, m16g, cs, gs);
        fused_layer<true><<<nGeneBlocks + nCellBlocks, 256, FUSED_SMEM>>>(
            cs, gs, col, nGeneBlocks);
    }
    {
        Side cs, gs;
        make_sides(m16c, m16g, out, out + (size_t)NCn * 128, cs, gs);
        fused_layer<false><<<nGeneBlocks + nCellBlocks, 256, FUSED_SMEM>>>(
            cs, gs, col, nGeneBlocks);
    }

    (void)in_sizes; (void)n_in; (void)out_size;
}